// round 1
// baseline (speedup 1.0000x reference)
#include <cuda_runtime.h>
#include <cstdint>

#define N_SAMP 2048
#define DIN    1024
#define DFEAT  2048
#define DIMF   128
#define CC     1000
#define QQ     8
#define NQ     8000      // Q*C
#define KNEG   1024
#define NCON   3075      // 2047 + 4 + 1024
#define NEGCNT 7992

// output layout (float32, tuple order, row-major flattened)
#define OFF_SIMCON 0ull
#define OFF_LABCON 6297600ull
#define OFF_LOGIT  12595200ull
#define OFF_QUEUE  14643200ull
#define OFF_QPTR   15667200ull

// ---------------- device scratch (no cudaMalloc allowed) ----------------
__device__ float g_mid [N_SAMP * DFEAT];
__device__ float g_h   [N_SAMP * DFEAT];
__device__ float g_hn  [N_SAMP * DFEAT];
__device__ float g_feat[N_SAMP * DIMF];
__device__ float g_simq[N_SAMP * NQ];
__device__ float g_psum[16 * DFEAT];
__device__ float g_psq [16 * DFEAT];
__device__ float g_mean[DFEAT];
__device__ float g_rstd[DFEAT];

// ---------------- generic 64x64x16 SGEMM: C = A(MxK) * B(KxN) + bias ----------------
__global__ void sgemm64(const float* __restrict__ A, const float* __restrict__ B,
                        const float* __restrict__ bias, float* __restrict__ C,
                        int M, int N, int K)
{
    __shared__ float As[16][65];
    __shared__ float Bs[16][64];
    const int tid = threadIdx.x;
    const int tx = tid & 15, ty = tid >> 4;
    const int rowBase = blockIdx.y * 64, colBase = blockIdx.x * 64;
    const int ar = tid >> 2, ak = (tid & 3) << 2;     // A tile: 64 rows x 16 k
    const int bkr = tid >> 4, bc = (tid & 15) << 2;   // B tile: 16 k x 64 cols
    float acc[4][4] = {};

    for (int k0 = 0; k0 < K; k0 += 16) {
        float4 a4 = *(const float4*)(A + (size_t)(rowBase + ar) * K + k0 + ak);
        As[ak + 0][ar] = a4.x; As[ak + 1][ar] = a4.y;
        As[ak + 2][ar] = a4.z; As[ak + 3][ar] = a4.w;

        int gc = colBase + bc;
        float4 b4;
        const float* brow = B + (size_t)(k0 + bkr) * N;
        if (gc + 3 < N) {
            b4 = *(const float4*)(brow + gc);
        } else {
            b4.x = (gc + 0 < N) ? brow[gc + 0] : 0.f;
            b4.y = (gc + 1 < N) ? brow[gc + 1] : 0.f;
            b4.z = (gc + 2 < N) ? brow[gc + 2] : 0.f;
            b4.w = (gc + 3 < N) ? brow[gc + 3] : 0.f;
        }
        *(float4*)&Bs[bkr][bc] = b4;
        __syncthreads();

        #pragma unroll
        for (int kk = 0; kk < 16; kk++) {
            float a0 = As[kk][ty * 4 + 0];
            float a1 = As[kk][ty * 4 + 1];
            float a2 = As[kk][ty * 4 + 2];
            float a3 = As[kk][ty * 4 + 3];
            float4 bb = *(const float4*)&Bs[kk][tx * 4];
            acc[0][0] += a0 * bb.x; acc[0][1] += a0 * bb.y; acc[0][2] += a0 * bb.z; acc[0][3] += a0 * bb.w;
            acc[1][0] += a1 * bb.x; acc[1][1] += a1 * bb.y; acc[1][2] += a1 * bb.z; acc[1][3] += a1 * bb.w;
            acc[2][0] += a2 * bb.x; acc[2][1] += a2 * bb.y; acc[2][2] += a2 * bb.z; acc[2][3] += a2 * bb.w;
            acc[3][0] += a3 * bb.x; acc[3][1] += a3 * bb.y; acc[3][2] += a3 * bb.z; acc[3][3] += a3 * bb.w;
        }
        __syncthreads();
    }

    #pragma unroll
    for (int i = 0; i < 4; i++) {
        int r = rowBase + ty * 4 + i;
        #pragma unroll
        for (int j = 0; j < 4; j++) {
            int c = colBase + tx * 4 + j;
            if (c < N) {
                float v = acc[i][j];
                if (bias) v += bias[c];
                C[(size_t)r * N + c] = v;
            }
        }
    }
}

// ---------------- sim_b = feat @ feat^T with off-diagonal compaction ----------------
__global__ void simb_offdiag(const float* __restrict__ feat, float* __restrict__ out)
{
    __shared__ float As[16][65];
    __shared__ float Bs[16][64];
    const int tid = threadIdx.x;
    const int tx = tid & 15, ty = tid >> 4;
    const int rowBase = blockIdx.y * 64, colBase = blockIdx.x * 64;
    const int ar = tid >> 2, ak = (tid & 3) << 2;
    const int bcc = tid & 63, bkq = (tid >> 6) << 2;
    float acc[4][4] = {};

    for (int k0 = 0; k0 < DIMF; k0 += 16) {
        float4 a4 = *(const float4*)(feat + (size_t)(rowBase + ar) * DIMF + k0 + ak);
        As[ak + 0][ar] = a4.x; As[ak + 1][ar] = a4.y;
        As[ak + 2][ar] = a4.z; As[ak + 3][ar] = a4.w;
        float4 b4 = *(const float4*)(feat + (size_t)(colBase + bcc) * DIMF + k0 + bkq);
        Bs[bkq + 0][bcc] = b4.x; Bs[bkq + 1][bcc] = b4.y;
        Bs[bkq + 2][bcc] = b4.z; Bs[bkq + 3][bcc] = b4.w;
        __syncthreads();
        #pragma unroll
        for (int kk = 0; kk < 16; kk++) {
            float a0 = As[kk][ty * 4 + 0];
            float a1 = As[kk][ty * 4 + 1];
            float a2 = As[kk][ty * 4 + 2];
            float a3 = As[kk][ty * 4 + 3];
            float4 bb = *(const float4*)&Bs[kk][tx * 4];
            acc[0][0] += a0 * bb.x; acc[0][1] += a0 * bb.y; acc[0][2] += a0 * bb.z; acc[0][3] += a0 * bb.w;
            acc[1][0] += a1 * bb.x; acc[1][1] += a1 * bb.y; acc[1][2] += a1 * bb.z; acc[1][3] += a1 * bb.w;
            acc[2][0] += a2 * bb.x; acc[2][1] += a2 * bb.y; acc[2][2] += a2 * bb.z; acc[2][3] += a2 * bb.w;
            acc[3][0] += a3 * bb.x; acc[3][1] += a3 * bb.y; acc[3][2] += a3 * bb.z; acc[3][3] += a3 * bb.w;
        }
        __syncthreads();
    }

    #pragma unroll
    for (int i = 0; i < 4; i++) {
        int r = rowBase + ty * 4 + i;
        #pragma unroll
        for (int j = 0; j < 4; j++) {
            int c = colBase + tx * 4 + j;
            if (c != r) {
                int oc = c - (c > r ? 1 : 0);
                out[(size_t)r * NCON + oc] = acc[i][j];
            }
        }
    }
}

// ---------------- batchnorm (deterministic two-stage) ----------------
__global__ void bn_partial(const float* __restrict__ h)
{
    int col = blockIdx.x * 256 + threadIdx.x;
    int r0 = blockIdx.y * 128;
    float s = 0.f, sq = 0.f;
    for (int i = 0; i < 128; i++) {
        float v = h[(size_t)(r0 + i) * DFEAT + col];
        s += v; sq += v * v;
    }
    g_psum[blockIdx.y * DFEAT + col] = s;
    g_psq [blockIdx.y * DFEAT + col] = sq;
}

__global__ void bn_final()
{
    int col = blockIdx.x * 256 + threadIdx.x;
    float s = 0.f, sq = 0.f;
    for (int i = 0; i < 16; i++) { s += g_psum[i * DFEAT + col]; sq += g_psq[i * DFEAT + col]; }
    float mean = s * (1.f / N_SAMP);
    float var  = sq * (1.f / N_SAMP) - mean * mean;
    g_mean[col] = mean;
    g_rstd[col] = rsqrtf(var + 1e-5f);
}

__global__ void bn_apply(const float* __restrict__ h, const float* __restrict__ gamma,
                         const float* __restrict__ beta, float* __restrict__ hn)
{
    int idx = blockIdx.x * 256 + threadIdx.x;
    int col = idx & (DFEAT - 1);
    float v = (h[idx] - g_mean[col]) * g_rstd[col] * gamma[col] + beta[col];
    hn[idx] = v > 0.f ? v : 0.f;
}

// ---------------- feat row L2 normalize (warp per row) ----------------
__global__ void feat_norm(float* feat)
{
    int w = threadIdx.x >> 5, lane = threadIdx.x & 31;
    int row = blockIdx.x * 8 + w;
    float4 v = *(float4*)(feat + (size_t)row * DIMF + lane * 4);
    float ss = v.x * v.x + v.y * v.y + v.z * v.z + v.w * v.w;
    #pragma unroll
    for (int o = 16; o; o >>= 1) ss += __shfl_xor_sync(0xffffffffu, ss, o);
    float r = rsqrtf(ss);
    v.x *= r; v.y *= r; v.z *= r; v.w *= r;
    *(float4*)(feat + (size_t)row * DIMF + lane * 4) = v;
}

// ---------------- pos_sel: 4 smallest of 8, ascending ----------------
__global__ void pos_sel(const float* __restrict__ simq, const int* __restrict__ labels,
                        float* __restrict__ out)
{
    int i = blockIdx.x * 256 + threadIdx.x;
    if (i >= N_SAMP) return;
    int L = labels[i];
    float v[8];
    #pragma unroll
    for (int k = 0; k < 8; k++) v[k] = simq[(size_t)i * NQ + L * 8 + k];
    #pragma unroll
    for (int a = 1; a < 8; a++) {
        float x = v[a]; int b = a - 1;
        while (b >= 0 && v[b] > x) { v[b + 1] = v[b]; b--; }
        v[b + 1] = x;
    }
    #pragma unroll
    for (int k = 0; k < 4; k++) out[(size_t)i * NCON + 2047 + k] = v[k];
}

// ---------------- neg top-1024 (sorted desc): per-row bitonic sort of 8192 ----------------
__global__ void neg_topk(const float* __restrict__ simq, const int* __restrict__ labels,
                         float* __restrict__ out)
{
    __shared__ float s[8192];
    const int i = blockIdx.x;
    const int tid = threadIdx.x;     // 1024 threads
    const int L = labels[i];
    const size_t base = (size_t)i * NQ;
    const float NEG_INF = __int_as_float(0xff800000);

    for (int t = tid; t < 8192; t += 1024) {
        float v = NEG_INF;
        if (t < NEGCNT) {
            int col = (t < 8 * L) ? t : t + 8;   // skip own-label block
            v = simq[base + col];
        }
        s[t] = v;
    }
    __syncthreads();

    for (int k = 2; k <= 8192; k <<= 1) {
        for (int j = k >> 1; j > 0; j >>= 1) {
            #pragma unroll 4
            for (int t = tid; t < 8192; t += 1024) {
                int ixj = t ^ j;
                if (ixj > t) {
                    bool up = ((t & k) == 0);
                    float a = s[t], b = s[ixj];
                    // descending overall
                    if (up ? (a < b) : (a > b)) { s[t] = b; s[ixj] = a; }
                }
            }
            __syncthreads();
        }
    }
    if (tid < KNEG) out[(size_t)i * NCON + 2051 + tid] = s[tid];
}

// ---------------- labels_con ----------------
__global__ void labcon(const int* __restrict__ labels, float* __restrict__ out)
{
    __shared__ int lab[N_SAMP];
    const int i = blockIdx.x;
    for (int t = threadIdx.x; t < N_SAMP; t += blockDim.x) lab[t] = labels[t];
    __syncthreads();
    int Li = lab[i];
    for (int j = threadIdx.x; j < NCON; j += blockDim.x) {
        float v;
        if (j < 2047) { int jj = j + (j >= i ? 1 : 0); v = (Li == lab[jj]) ? 1.f : 0.f; }
        else if (j < 2051) v = 1.f;
        else v = 0.f;
        out[(size_t)i * NCON + j] = v;
    }
}

// ---------------- queue: copy then sequential scan ----------------
__global__ void qcopy(const float* __restrict__ src, float* __restrict__ dst)
{
    int t = blockIdx.x * 256 + threadIdx.x;
    if (t < DIMF * NQ) dst[t] = src[t];
}

__global__ void queue_scan(const float* __restrict__ feat, const int* __restrict__ labels,
                           const int* __restrict__ qptr, float* __restrict__ outq,
                           float* __restrict__ outp)
{
    __shared__ int qp[CC];
    __shared__ int lab[N_SAMP / 2];
    const int tid = threadIdx.x;     // 128 threads, one per dim
    for (int t = tid; t < CC; t += 128) qp[t] = qptr[t];
    for (int t = tid; t < N_SAMP / 2; t += 128) lab[t] = labels[t];
    __syncthreads();
    for (int i = 0; i < N_SAMP / 2; i++) {
        int c = lab[i];
        int ptr = qp[c];
        outq[(size_t)tid * NQ + c * QQ + ptr] = feat[(size_t)i * DIMF + tid];
        __syncthreads();
        if (tid == 0) qp[c] = (ptr + 1) & (QQ - 1);
        __syncthreads();
    }
    for (int t = tid; t < CC; t += 128) outp[t] = (float)qp[t];
}

// ---------------- launch ----------------
extern "C" void kernel_launch(void* const* d_in, const int* in_sizes, int n_in,
                              void* d_out, int out_size)
{
    const float* img    = (const float*)d_in[0];
    const int*   labels = (const int*)  d_in[1];
    const float* qlist  = (const float*)d_in[2];
    const int*   qptr   = (const int*)  d_in[3];
    // d_in[4] pos_index, d_in[5] neg_index: structure is analytic, unused
    const float* enc_W  = (const float*)d_in[6];
    const float* enc_b  = (const float*)d_in[7];
    const float* W1     = (const float*)d_in[8];
    const float* b1     = (const float*)d_in[9];
    const float* gamma  = (const float*)d_in[10];
    const float* beta   = (const float*)d_in[11];
    const float* W2     = (const float*)d_in[12];
    const float* b2     = (const float*)d_in[13];
    const float* linW   = (const float*)d_in[14];
    const float* linb   = (const float*)d_in[15];
    float* out = (float*)d_out;

    float *mid, *h, *hn, *feat, *simq;
    cudaGetSymbolAddress((void**)&mid,  g_mid);
    cudaGetSymbolAddress((void**)&h,    g_h);
    cudaGetSymbolAddress((void**)&hn,   g_hn);
    cudaGetSymbolAddress((void**)&feat, g_feat);
    cudaGetSymbolAddress((void**)&simq, g_simq);

    // mid = img @ enc_W + enc_b
    sgemm64<<<dim3(DFEAT / 64, N_SAMP / 64), 256>>>(img, enc_W, enc_b, mid, N_SAMP, DFEAT, DIN);
    // h = mid @ W1 + b1
    sgemm64<<<dim3(DFEAT / 64, N_SAMP / 64), 256>>>(mid, W1, b1, h, N_SAMP, DFEAT, DFEAT);
    // batchnorm + relu -> hn
    bn_partial<<<dim3(DFEAT / 256, 16), 256>>>(h);
    bn_final<<<DFEAT / 256, 256>>>();
    bn_apply<<<(N_SAMP * DFEAT) / 256, 256>>>(h, gamma, beta, hn);
    // feat = hn @ W2 + b2, then L2-normalize rows
    sgemm64<<<dim3(DIMF / 64, N_SAMP / 64), 256>>>(hn, W2, b2, feat, N_SAMP, DIMF, DFEAT);
    feat_norm<<<N_SAMP / 8, 256>>>(feat);
    // logit_cls = mid @ linW + linb  (directly into output)
    sgemm64<<<dim3((CC + 63) / 64, N_SAMP / 64), 256>>>(mid, linW, linb, out + OFF_LOGIT, N_SAMP, CC, DFEAT);
    // sim_q = feat @ queue_list
    sgemm64<<<dim3(NQ / 64, N_SAMP / 64), 256>>>(feat, qlist, nullptr, simq, N_SAMP, NQ, DIMF);
    // sim_b off-diagonal -> sim_con[:, 0:2047]
    simb_offdiag<<<dim3(N_SAMP / 64, N_SAMP / 64), 256>>>(feat, out + OFF_SIMCON);
    // pos / neg selections
    pos_sel<<<N_SAMP / 256, 256>>>(simq, labels, out + OFF_SIMCON);
    neg_topk<<<N_SAMP, 1024>>>(simq, labels, out + OFF_SIMCON);
    // labels_con
    labcon<<<N_SAMP, 256>>>(labels, out + OFF_LABCON);
    // queue update
    qcopy<<<(DIMF * NQ) / 256, 256>>>(qlist, out + OFF_QUEUE);
    queue_scan<<<1, 128>>>(feat, labels, qptr, out + OFF_QUEUE, out + OFF_QPTR);
}

// round 4
// speedup vs baseline: 2.5697x; 2.5697x over previous
#include <cuda_runtime.h>
#include <cuda_bf16.h>
#include <cstdint>

#define N_SAMP 2048
#define DIN    1024
#define DFEAT  2048
#define DIMF   128
#define CC     1000
#define QQ     8
#define NQ     8000      // Q*C (queue width in output)
#define NQS    8064      // padded sim_q stride (63 * 128)
#define KNEG   1024
#define NCON   3075      // 2047 + 4 + 1024
#define NEGCNT 7992

// output layout (float32, tuple order, row-major flattened)
#define OFF_SIMCON 0ull
#define OFF_LABCON 6297600ull
#define OFF_LOGIT  12595200ull
#define OFF_QUEUE  14643200ull
#define OFF_QPTR   15667200ull

// ---------------- device scratch (no cudaMalloc allowed) ----------------
__device__ float g_mid [N_SAMP * DFEAT];
__device__ float g_h   [N_SAMP * DFEAT];
__device__ float g_hn  [N_SAMP * DFEAT];
__device__ float g_feat[N_SAMP * DIMF];
__device__ float g_simq[N_SAMP * NQS];
__device__ float g_psum[16 * DFEAT];
__device__ float g_psq [16 * DFEAT];
__device__ float g_mean[DFEAT];
__device__ float g_rstd[DFEAT];
__device__ __nv_bfloat16 g_ahi[N_SAMP * DFEAT];
__device__ __nv_bfloat16 g_alo[N_SAMP * DFEAT];
__device__ __nv_bfloat16 g_bhi[NQS * DIMF > DFEAT * DFEAT ? NQS * DIMF : DFEAT * DFEAT];
__device__ __nv_bfloat16 g_blo[NQS * DIMF > DFEAT * DFEAT ? NQS * DIMF : DFEAT * DFEAT];

// ================= helpers =================
__device__ __forceinline__ uint32_t smem_u32(const void* p) {
    uint32_t a;
    asm("{ .reg .u64 t; cvta.to.shared.u64 t, %1; cvt.u32.u64 %0, t; }" : "=r"(a) : "l"(p));
    return a;
}
__device__ __forceinline__ void cpa16(uint32_t s, const void* g) {
    asm volatile("cp.async.cg.shared.global [%0], [%1], 16;" :: "r"(s), "l"(g) : "memory");
}
__device__ __forceinline__ void ldsm4(uint32_t* r, uint32_t addr) {
    asm volatile("ldmatrix.sync.aligned.m8n8.x4.shared.b16 {%0,%1,%2,%3}, [%4];"
                 : "=r"(r[0]), "=r"(r[1]), "=r"(r[2]), "=r"(r[3]) : "r"(addr));
}
__device__ __forceinline__ void ldsm2(uint32_t* r, uint32_t addr) {
    asm volatile("ldmatrix.sync.aligned.m8n8.x2.shared.b16 {%0,%1}, [%2];"
                 : "=r"(r[0]), "=r"(r[1]) : "r"(addr));
}
__device__ __forceinline__ void mma_bf16(float* c, const uint32_t* a, const uint32_t* b) {
    asm volatile("mma.sync.aligned.m16n8k16.row.col.f32.bf16.bf16.f32 "
                 "{%0,%1,%2,%3}, {%4,%5,%6,%7}, {%8,%9}, {%0,%1,%2,%3};"
                 : "+f"(c[0]), "+f"(c[1]), "+f"(c[2]), "+f"(c[3])
                 : "r"(a[0]), "r"(a[1]), "r"(a[2]), "r"(a[3]), "r"(b[0]), "r"(b[1]));
}

// ================= split-bf16 MMA GEMM: C[2048 x Npad] = A @ B^T =================
// Ahi/Alo: bf16 [M,K] row-major. Bhi/Blo: bf16 [Npad,K] row-major.
// Tile 128x128, BK=32, double-buffered cp.async. 3-pass split for fp32 accuracy.
// mode: 0 plain (+bias), 1 offdiag-compact, 2 bounded cols < nbound (+bias)
#define STG 40960         // bytes per stage (4 arrays x 128 rows x 80B)
#define SMEM_GEMM (2 * STG)

__global__ void __launch_bounds__(256) gemm_mma(
    const __nv_bfloat16* __restrict__ Ahi, const __nv_bfloat16* __restrict__ Alo,
    const __nv_bfloat16* __restrict__ Bhi, const __nv_bfloat16* __restrict__ Blo,
    const float* __restrict__ bias, float* __restrict__ C,
    int K, int ldC, int mode, int nbound)
{
    extern __shared__ __align__(128) char sm[];
    const uint32_t sb = smem_u32(sm);
    const int tid = threadIdx.x, wid = tid >> 5, lane = tid & 31;
    const int rowBase = blockIdx.y * 128, nBase = blockIdx.x * 128;
    const int nch = K >> 5;

    float acc[4][4][4];
    #pragma unroll
    for (int i = 0; i < 4; i++)
        #pragma unroll
        for (int j = 0; j < 4; j++)
            #pragma unroll
            for (int q = 0; q < 4; q++) acc[i][j][q] = 0.f;

    const int lrow = tid >> 1;
    const uint32_t so = lrow * 80 + (tid & 1) * 32;
    const size_t gaRow = (size_t)(rowBase + lrow) * K + (tid & 1) * 16;
    const size_t gbRow = (size_t)(nBase  + lrow) * K + (tid & 1) * 16;

#define ISSUE(st, ch) do {                                                   \
        const int k0_ = (ch) << 5;                                           \
        const uint32_t B0_ = sb + (st) * STG;                                \
        cpa16(B0_ + so,              Ahi + gaRow + k0_);                     \
        cpa16(B0_ + so + 16,         Ahi + gaRow + k0_ + 8);                 \
        cpa16(B0_ + 10240 + so,      Alo + gaRow + k0_);                     \
        cpa16(B0_ + 10240 + so + 16, Alo + gaRow + k0_ + 8);                 \
        cpa16(B0_ + 20480 + so,      Bhi + gbRow + k0_);                     \
        cpa16(B0_ + 20480 + so + 16, Bhi + gbRow + k0_ + 8);                 \
        cpa16(B0_ + 30720 + so,      Blo + gbRow + k0_);                     \
        cpa16(B0_ + 30720 + so + 16, Blo + gbRow + k0_ + 8);                 \
        asm volatile("cp.async.commit_group;" ::: "memory");                 \
    } while (0)

    ISSUE(0, 0);

    const int wm = (wid >> 2) * 64, wn = (wid & 3) * 32;
    const int arow = lane & 15, ahalf = lane >> 4;
    const int brow = lane & 7,  bhalf = (lane >> 3) & 1;

    for (int ch = 0; ch < nch; ch++) {
        if (ch + 1 < nch) {
            ISSUE((ch + 1) & 1, ch + 1);
            asm volatile("cp.async.wait_group 1;" ::: "memory");
        } else {
            asm volatile("cp.async.wait_group 0;" ::: "memory");
        }
        __syncthreads();
        const uint32_t base = sb + (ch & 1) * STG;

        #pragma unroll
        for (int ks = 0; ks < 2; ks++) {
            uint32_t fahi[4][4], falo[4][4], fbhi[4][2], fblo[4][2];
            #pragma unroll
            for (int mi = 0; mi < 4; mi++) {
                uint32_t ad = base + (wm + mi * 16 + arow) * 80 + ks * 32 + ahalf * 16;
                ldsm4(fahi[mi], ad);
                ldsm4(falo[mi], ad + 10240);
            }
            #pragma unroll
            for (int ni = 0; ni < 4; ni++) {
                uint32_t bd = base + 20480 + (wn + ni * 8 + brow) * 80 + ks * 32 + bhalf * 16;
                ldsm2(fbhi[ni], bd);
                ldsm2(fblo[ni], bd + 10240);
            }
            #pragma unroll
            for (int mi = 0; mi < 4; mi++)
                #pragma unroll
                for (int ni = 0; ni < 4; ni++) {
                    mma_bf16(acc[mi][ni], fahi[mi], fbhi[ni]);
                    mma_bf16(acc[mi][ni], fahi[mi], fblo[ni]);
                    mma_bf16(acc[mi][ni], falo[mi], fbhi[ni]);
                }
        }
        __syncthreads();
    }
#undef ISSUE

    // ---- epilogue ----
    const int qrow = lane >> 2, qcol = (lane & 3) * 2;
    #pragma unroll
    for (int mi = 0; mi < 4; mi++) {
        #pragma unroll
        for (int hh = 0; hh < 2; hh++) {
            const int r = rowBase + wm + mi * 16 + qrow + hh * 8;
            #pragma unroll
            for (int ni = 0; ni < 4; ni++) {
                const int c = nBase + wn + ni * 8 + qcol;
                float v0 = acc[mi][ni][hh * 2 + 0];
                float v1 = acc[mi][ni][hh * 2 + 1];
                if (mode == 0) {
                    if (bias) { v0 += bias[c]; v1 += bias[c + 1]; }
                    *(float2*)(C + (size_t)r * ldC + c) = make_float2(v0, v1);
                } else if (mode == 1) {
                    if (c != r)     C[(size_t)r * ldC + c     - (c     > r ? 1 : 0)] = v0;
                    if (c + 1 != r) C[(size_t)r * ldC + c + 1 - (c + 1 > r ? 1 : 0)] = v1;
                } else {
                    if (c < nbound)     C[(size_t)r * ldC + c]     = v0 + (bias ? bias[c]     : 0.f);
                    if (c + 1 < nbound) C[(size_t)r * ldC + c + 1] = v1 + (bias ? bias[c + 1] : 0.f);
                }
            }
        }
    }
}

// ============ weight prep: fp32 W[K,N] -> bf16 hi/lo [Npad,K] (transpose + split) ============
__global__ void conv_w(const float* __restrict__ W, __nv_bfloat16* __restrict__ hi,
                       __nv_bfloat16* __restrict__ lo, int K, int N)
{
    __shared__ float ts[32][33];
    const int c = threadIdx.x & 31, r8 = threadIdx.x >> 5;
    const int nb = blockIdx.x * 32, kb = blockIdx.y * 32;
    #pragma unroll
    for (int rr = r8; rr < 32; rr += 8) {
        int n = nb + c;
        ts[rr][c] = (n < N) ? W[(size_t)(kb + rr) * N + n] : 0.f;
    }
    __syncthreads();
    #pragma unroll
    for (int rr = r8; rr < 32; rr += 8) {
        float v = ts[c][rr];
        __nv_bfloat16 h = __float2bfloat16(v);
        __nv_bfloat16 l = __float2bfloat16(v - __bfloat162float(h));
        size_t o = (size_t)(nb + rr) * K + kb + c;
        hi[o] = h; lo[o] = l;
    }
}

// ============ plain split: fp32 row-major -> bf16 hi/lo same layout ============
__global__ void conv_plain(const float* __restrict__ X, __nv_bfloat16* __restrict__ hi,
                           __nv_bfloat16* __restrict__ lo, int n)
{
    int i = blockIdx.x * 256 + threadIdx.x;
    if (i >= n) return;
    float v = X[i];
    __nv_bfloat16 h = __float2bfloat16(v);
    hi[i] = h;
    lo[i] = __float2bfloat16(v - __bfloat162float(h));
}

// ---------------- batchnorm (deterministic two-stage) ----------------
__global__ void bn_partial(const float* __restrict__ h)
{
    int col = blockIdx.x * 256 + threadIdx.x;
    int r0 = blockIdx.y * 128;
    float s = 0.f, sq = 0.f;
    for (int i = 0; i < 128; i++) {
        float v = h[(size_t)(r0 + i) * DFEAT + col];
        s += v; sq += v * v;
    }
    g_psum[blockIdx.y * DFEAT + col] = s;
    g_psq [blockIdx.y * DFEAT + col] = sq;
}

__global__ void bn_final()
{
    int col = blockIdx.x * 256 + threadIdx.x;
    float s = 0.f, sq = 0.f;
    for (int i = 0; i < 16; i++) { s += g_psum[i * DFEAT + col]; sq += g_psq[i * DFEAT + col]; }
    float mean = s * (1.f / N_SAMP);
    float var  = sq * (1.f / N_SAMP) - mean * mean;
    g_mean[col] = mean;
    g_rstd[col] = rsqrtf(var + 1e-5f);
}

__global__ void bn_apply(const float* __restrict__ h, const float* __restrict__ gamma,
                         const float* __restrict__ beta, float* __restrict__ hn)
{
    int idx = blockIdx.x * 256 + threadIdx.x;
    int col = idx & (DFEAT - 1);
    float v = (h[idx] - g_mean[col]) * g_rstd[col] * gamma[col] + beta[col];
    hn[idx] = v > 0.f ? v : 0.f;
}

// ---------------- feat row L2 normalize (warp per row) ----------------
__global__ void feat_norm(float* feat)
{
    int w = threadIdx.x >> 5, lane = threadIdx.x & 31;
    int row = blockIdx.x * 8 + w;
    float4 v = *(float4*)(feat + (size_t)row * DIMF + lane * 4);
    float ss = v.x * v.x + v.y * v.y + v.z * v.z + v.w * v.w;
    #pragma unroll
    for (int o = 16; o; o >>= 1) ss += __shfl_xor_sync(0xffffffffu, ss, o);
    float r = rsqrtf(ss);
    v.x *= r; v.y *= r; v.z *= r; v.w *= r;
    *(float4*)(feat + (size_t)row * DIMF + lane * 4) = v;
}

// ---------------- pos_sel: 4 smallest of 8, ascending ----------------
__global__ void pos_sel(const float* __restrict__ simq, const int* __restrict__ labels,
                        float* __restrict__ out)
{
    int i = blockIdx.x * 256 + threadIdx.x;
    if (i >= N_SAMP) return;
    int L = labels[i];
    float v[8];
    #pragma unroll
    for (int k = 0; k < 8; k++) v[k] = simq[(size_t)i * NQS + L * 8 + k];
    #pragma unroll
    for (int a = 1; a < 8; a++) {
        float x = v[a]; int b = a - 1;
        while (b >= 0 && v[b] > x) { v[b + 1] = v[b]; b--; }
        v[b + 1] = x;
    }
    #pragma unroll
    for (int k = 0; k < 4; k++) out[(size_t)i * NCON + 2047 + k] = v[k];
}

// ---------------- neg top-1024 (sorted desc): radix select + 1024 bitonic ----------------
__global__ void __launch_bounds__(256) neg_topk(const float* __restrict__ simq,
                                                const int* __restrict__ labels,
                                                float* __restrict__ out)
{
    __shared__ uint32_t keys[NEGCNT];
    __shared__ uint32_t buf[KNEG];
    __shared__ int hist[256];
    __shared__ int sh_prefix, sh_target, sh_cnt;
    const int i = blockIdx.x, tid = threadIdx.x;
    const int L = labels[i];
    const size_t base = (size_t)i * NQS;

    for (int t = tid; t < NEGCNT; t += 256) {
        int col = (t < 8 * L) ? t : t + 8;
        uint32_t b = __float_as_uint(simq[base + col]);
        keys[t] = (b >> 31) ? ~b : (b | 0x80000000u);
    }
    if (tid == 0) { sh_target = KNEG; sh_prefix = 0; sh_cnt = 0; }
    __syncthreads();

    uint32_t prefix = 0;
    #pragma unroll
    for (int pass = 0; pass < 4; pass++) {
        const int shift = 24 - pass * 8;
        hist[tid] = 0;
        __syncthreads();
        for (int t = tid; t < NEGCNT; t += 256) {
            uint32_t u = keys[t];
            bool ok = (pass == 0) || ((u >> (shift + 8)) == prefix);
            if (ok) atomicAdd(&hist[(u >> shift) & 255], 1);
        }
        __syncthreads();
        if (tid == 0) {
            int need = sh_target, acc = 0, b = 255;
            while (acc + hist[b] < need) { acc += hist[b]; b--; }
            sh_prefix = (int)((prefix << 8) | (uint32_t)b);
            sh_target = need - acc;
        }
        __syncthreads();
        prefix = (uint32_t)sh_prefix;
    }
    const uint32_t T = prefix;
    const int G = KNEG - sh_target;
    __syncthreads();

    for (int t = tid; t < NEGCNT; t += 256) {
        uint32_t u = keys[t];
        if (u > T) { int p = atomicAdd(&sh_cnt, 1); buf[p] = u; }
    }
    __syncthreads();
    for (int p = G + tid; p < KNEG; p += 256) buf[p] = T;
    __syncthreads();

    for (int k = 2; k <= KNEG; k <<= 1) {
        for (int j = k >> 1; j > 0; j >>= 1) {
            #pragma unroll
            for (int q = 0; q < 4; q++) {
                int t = tid + q * 256;
                int ixj = t ^ j;
                if (ixj > t) {
                    uint32_t a = buf[t], b = buf[ixj];
                    bool up = ((t & k) == 0);
                    if (up ? (a < b) : (a > b)) { buf[t] = b; buf[ixj] = a; }
                }
            }
            __syncthreads();
        }
    }
    #pragma unroll
    for (int q = 0; q < 4; q++) {
        int t = tid + q * 256;
        uint32_t u = buf[t];
        uint32_t bits = (u & 0x80000000u) ? (u & 0x7fffffffu) : ~u;
        out[(size_t)i * NCON + 2051 + t] = __uint_as_float(bits);
    }
}

// ---------------- labels_con ----------------
__global__ void labcon(const int* __restrict__ labels, float* __restrict__ out)
{
    __shared__ int lab[N_SAMP];
    const int i = blockIdx.x;
    for (int t = threadIdx.x; t < N_SAMP; t += blockDim.x) lab[t] = labels[t];
    __syncthreads();
    int Li = lab[i];
    for (int j = threadIdx.x; j < NCON; j += blockDim.x) {
        float v;
        if (j < 2047) { int jj = j + (j >= i ? 1 : 0); v = (Li == lab[jj]) ? 1.f : 0.f; }
        else if (j < 2051) v = 1.f;
        else v = 0.f;
        out[(size_t)i * NCON + j] = v;
    }
}

// ---------------- queue: copy then sequential scan ----------------
__global__ void qcopy(const float* __restrict__ src, float* __restrict__ dst)
{
    int t = blockIdx.x * 256 + threadIdx.x;
    if (t < DIMF * NQ) dst[t] = src[t];
}

__global__ void queue_scan(const float* __restrict__ feat, const int* __restrict__ labels,
                           const int* __restrict__ qptr, float* __restrict__ outq,
                           float* __restrict__ outp)
{
    __shared__ int qp[CC];
    __shared__ int lab[N_SAMP / 2];
    const int tid = threadIdx.x;     // 128 threads, one per dim
    for (int t = tid; t < CC; t += 128) qp[t] = qptr[t];
    for (int t = tid; t < N_SAMP / 2; t += 128) lab[t] = labels[t];
    __syncthreads();
    for (int i = 0; i < N_SAMP / 2; i++) {
        int c = lab[i];
        int ptr = qp[c];
        outq[(size_t)tid * NQ + c * QQ + ptr] = feat[(size_t)i * DIMF + tid];
        __syncthreads();
        if (tid == 0) qp[c] = (ptr + 1) & (QQ - 1);
        __syncthreads();
    }
    for (int t = tid; t < CC; t += 128) outp[t] = (float)qp[t];
}

// ---------------- launch ----------------
extern "C" void kernel_launch(void* const* d_in, const int* in_sizes, int n_in,
                              void* d_out, int out_size)
{
    const float* img    = (const float*)d_in[0];
    const int*   labels = (const int*)  d_in[1];
    const float* qlist  = (const float*)d_in[2];
    const int*   qptr   = (const int*)  d_in[3];
    const float* enc_W  = (const float*)d_in[6];
    const float* enc_b  = (const float*)d_in[7];
    const float* W1     = (const float*)d_in[8];
    const float* b1     = (const float*)d_in[9];
    const float* gamma  = (const float*)d_in[10];
    const float* beta   = (const float*)d_in[11];
    const float* W2     = (const float*)d_in[12];
    const float* b2     = (const float*)d_in[13];
    const float* linW   = (const float*)d_in[14];
    const float* linb   = (const float*)d_in[15];
    float* out = (float*)d_out;

    float *mid, *h, *hn, *feat, *simq;
    __nv_bfloat16 *ahi, *alo, *bhi, *blo;
    cudaGetSymbolAddress((void**)&mid,  g_mid);
    cudaGetSymbolAddress((void**)&h,    g_h);
    cudaGetSymbolAddress((void**)&hn,   g_hn);
    cudaGetSymbolAddress((void**)&feat, g_feat);
    cudaGetSymbolAddress((void**)&simq, g_simq);
    cudaGetSymbolAddress((void**)&ahi,  g_ahi);
    cudaGetSymbolAddress((void**)&alo,  g_alo);
    cudaGetSymbolAddress((void**)&bhi,  g_bhi);
    cudaGetSymbolAddress((void**)&blo,  g_blo);

    cudaFuncSetAttribute(gemm_mma, cudaFuncAttributeMaxDynamicSharedMemorySize, SMEM_GEMM);

    // ---- mid = img @ enc_W + enc_b   (K=1024, N=2048) ----
    conv_plain<<<(N_SAMP * DIN + 255) / 256, 256>>>(img, ahi, alo, N_SAMP * DIN);
    conv_w<<<dim3(DFEAT / 32, DIN / 32), 256>>>(enc_W, bhi, blo, DIN, DFEAT);
    gemm_mma<<<dim3(16, 16), 256, SMEM_GEMM>>>(ahi, alo, bhi, blo, enc_b, mid, DIN, DFEAT, 0, 0);

    // ---- h = mid @ W1 + b1  AND  logit = mid @ linW + linb (share A=mid) ----
    conv_plain<<<(N_SAMP * DFEAT + 255) / 256, 256>>>(mid, ahi, alo, N_SAMP * DFEAT);
    conv_w<<<dim3(DFEAT / 32, DFEAT / 32), 256>>>(W1, bhi, blo, DFEAT, DFEAT);
    gemm_mma<<<dim3(16, 16), 256, SMEM_GEMM>>>(ahi, alo, bhi, blo, b1, h, DFEAT, DFEAT, 0, 0);
    conv_w<<<dim3(1024 / 32, DFEAT / 32), 256>>>(linW, bhi, blo, DFEAT, CC);
    gemm_mma<<<dim3(8, 16), 256, SMEM_GEMM>>>(ahi, alo, bhi, blo, linb, out + OFF_LOGIT, DFEAT, CC, 2, CC);

    // ---- batchnorm + relu -> hn ----
    bn_partial<<<dim3(DFEAT / 256, 16), 256>>>(h);
    bn_final<<<DFEAT / 256, 256>>>();
    bn_apply<<<(N_SAMP * DFEAT) / 256, 256>>>(h, gamma, beta, hn);

    // ---- feat = hn @ W2 + b2  (K=2048, N=128) ----
    conv_plain<<<(N_SAMP * DFEAT + 255) / 256, 256>>>(hn, ahi, alo, N_SAMP * DFEAT);
    conv_w<<<dim3(DIMF / 32, DFEAT / 32), 256>>>(W2, bhi, blo, DFEAT, DIMF);
    gemm_mma<<<dim3(1, 16), 256, SMEM_GEMM>>>(ahi, alo, bhi, blo, b2, feat, DFEAT, DIMF, 0, 0);
    feat_norm<<<N_SAMP / 8, 256>>>(feat);

    // ---- feat bf16 split (A for sim_b/sim_q; also serves as B for sim_b) ----
    conv_plain<<<(N_SAMP * DIMF + 255) / 256, 256>>>(feat, ahi, alo, N_SAMP * DIMF);
    // sim_b off-diagonal -> sim_con[:, 0:2047]   (B = feat split itself)
    gemm_mma<<<dim3(16, 16), 256, SMEM_GEMM>>>(ahi, alo, ahi, alo, nullptr, out + OFF_SIMCON, DIMF, NCON, 1, 0);
    // sim_q = feat @ queue_list  (K=128, N=8000 padded to 8064)
    conv_w<<<dim3(NQS / 32, DIMF / 32), 256>>>(qlist, bhi, blo, DIMF, NQ);
    gemm_mma<<<dim3(63, 16), 256, SMEM_GEMM>>>(ahi, alo, bhi, blo, nullptr, simq, DIMF, NQS, 0, 0);

    // ---- selections ----
    pos_sel<<<N_SAMP / 256, 256>>>(simq, labels, out + OFF_SIMCON);
    neg_topk<<<N_SAMP, 256>>>(simq, labels, out + OFF_SIMCON);
    labcon<<<N_SAMP, 256>>>(labels, out + OFF_LABCON);

    // ---- queue update ----
    qcopy<<<(DIMF * NQ) / 256, 256>>>(qlist, out + OFF_QUEUE);
    queue_scan<<<1, 128>>>(feat, labels, qptr, out + OFF_QUEUE, out + OFF_QPTR);
}

// round 5
// speedup vs baseline: 2.9921x; 1.1643x over previous
#include <cuda_runtime.h>
#include <cuda_bf16.h>
#include <cstdint>

#define N_SAMP 2048
#define DIN    1024
#define DFEAT  2048
#define DIMF   128
#define CC     1000
#define QQ     8
#define NQ     8000
#define NQS    8192      // padded sim_q stride
#define KNEG   1024
#define NCON   3075      // 2047 + 4 + 1024
#define NEGCNT 7992

// output layout (float32, tuple order, row-major flattened)
#define OFF_SIMCON 0ull
#define OFF_LABCON 6297600ull
#define OFF_LOGIT  12595200ull
#define OFF_QUEUE  14643200ull
#define OFF_QPTR   15667200ull

// ---------------- device scratch (no cudaMalloc allowed) ----------------
__device__ float g_h   [N_SAMP * DFEAT];
__device__ float g_simq[N_SAMP * NQS];
__device__ float g_feat[N_SAMP * DIMF];
__device__ float g_fpart[4 * N_SAMP * DIMF];
__device__ float g_psum[16 * DFEAT];
__device__ float g_psq [16 * DFEAT];
__device__ float g_mean[DFEAT];
__device__ float g_rstd[DFEAT];
__device__ __nv_bfloat16 g_ahi[DFEAT * DFEAT];   // mid split
__device__ __nv_bfloat16 g_alo[DFEAT * DFEAT];
__device__ __nv_bfloat16 g_chi[DFEAT * DFEAT];   // img split, then hn split
__device__ __nv_bfloat16 g_clo[DFEAT * DFEAT];
__device__ __nv_bfloat16 g_bhi[DFEAT * DFEAT];   // B-side (weights), reused
__device__ __nv_bfloat16 g_blo[DFEAT * DFEAT];
__device__ __nv_bfloat16 g_fhi[N_SAMP * DIMF];   // feat split
__device__ __nv_bfloat16 g_flo[N_SAMP * DIMF];

// ================= helpers =================
__device__ __forceinline__ uint32_t smem_u32(const void* p) {
    uint32_t a;
    asm("{ .reg .u64 t; cvta.to.shared.u64 t, %1; cvt.u32.u64 %0, t; }" : "=r"(a) : "l"(p));
    return a;
}
__device__ __forceinline__ void cpa16(uint32_t s, const void* g) {
    asm volatile("cp.async.cg.shared.global [%0], [%1], 16;" :: "r"(s), "l"(g) : "memory");
}
__device__ __forceinline__ void ldsm4(uint32_t* r, uint32_t addr) {
    asm volatile("ldmatrix.sync.aligned.m8n8.x4.shared.b16 {%0,%1,%2,%3}, [%4];"
                 : "=r"(r[0]), "=r"(r[1]), "=r"(r[2]), "=r"(r[3]) : "r"(addr));
}
__device__ __forceinline__ void ldsm2(uint32_t* r, uint32_t addr) {
    asm volatile("ldmatrix.sync.aligned.m8n8.x2.shared.b16 {%0,%1}, [%2];"
                 : "=r"(r[0]), "=r"(r[1]) : "r"(addr));
}
__device__ __forceinline__ void mma_bf16(float* c, const uint32_t* a, const uint32_t* b) {
    asm volatile("mma.sync.aligned.m16n8k16.row.col.f32.bf16.bf16.f32 "
                 "{%0,%1,%2,%3}, {%4,%5,%6,%7}, {%8,%9}, {%0,%1,%2,%3};"
                 : "+f"(c[0]), "+f"(c[1]), "+f"(c[2]), "+f"(c[3])
                 : "r"(a[0]), "r"(a[1]), "r"(a[2]), "r"(a[3]), "r"(b[0]), "r"(b[1]));
}
__device__ __forceinline__ void split_bf(float v, __nv_bfloat16& h, __nv_bfloat16& l) {
    h = __float2bfloat16(v);
    l = __float2bfloat16(v - __bfloat162float(h));
}

// ================= split-bf16 MMA GEMM: C[M x Ntile*grid] = A @ B^T =================
// Tile 128 x (NI*32). BK=32, double-buffered cp.async, 3-pass split accuracy.
// mode: 0 fp32(+bias), 1 offdiag-compact, 2 bounded cols(+bias), 3 bf16 split out(+bias),
//       4 split-K partial fp32 (offset blockIdx.z)
template<int NI>
__global__ void __launch_bounds__(256, 1) gemm_mma(
    const __nv_bfloat16* __restrict__ Ahi, const __nv_bfloat16* __restrict__ Alo,
    const __nv_bfloat16* __restrict__ Bhi, const __nv_bfloat16* __restrict__ Blo,
    const float* __restrict__ bias, float* __restrict__ C,
    __nv_bfloat16* __restrict__ Ohi, __nv_bfloat16* __restrict__ Olo,
    int K, int Ksub, int ldC, int mode, int nbound)
{
    constexpr uint32_t SA_LO = 10240;            // 128*80
    constexpr uint32_t SB_HI = 20480;
    constexpr uint32_t SB_LO = 20480 + NI * 2560;  // NI*32*80
    constexpr uint32_t STAGE = 20480 + 2 * NI * 2560;

    extern __shared__ __align__(128) char sm[];
    const uint32_t sb = smem_u32(sm);
    const int tid = threadIdx.x, wid = tid >> 5, lane = tid & 31;
    const int rowBase = blockIdx.y * 128, nBase = blockIdx.x * (NI * 32);
    const int kbase = blockIdx.z * Ksub;
    const int nch = Ksub >> 5;

    float acc[4][NI][4];
    #pragma unroll
    for (int i = 0; i < 4; i++)
        #pragma unroll
        for (int j = 0; j < NI; j++)
            #pragma unroll
            for (int q = 0; q < 4; q++) acc[i][j][q] = 0.f;

    const int ldRow = tid >> 2, ldSeg = tid & 3;
    const uint32_t aoff = ldRow * 80 + ldSeg * 16;
    const size_t ga = (size_t)(rowBase + ldRow) * K + ldSeg * 8 + kbase;
    const size_t gb = (size_t)(nBase  + ldRow) * K + ldSeg * 8 + kbase;

#define ISSUE(st, ch) do {                                                        \
        const int k0_ = (ch) << 5;                                                \
        const uint32_t B0_ = sb + (st) * STAGE;                                   \
        cpa16(B0_ + aoff,                 Ahi + ga + k0_);                        \
        cpa16(B0_ + aoff + 64*80,         Ahi + ga + (size_t)64*K + k0_);         \
        cpa16(B0_ + SA_LO + aoff,         Alo + ga + k0_);                        \
        cpa16(B0_ + SA_LO + aoff + 64*80, Alo + ga + (size_t)64*K + k0_);         \
        _Pragma("unroll")                                                         \
        for (int it = 0; it < NI / 2; it++) {                                     \
            cpa16(B0_ + SB_HI + aoff + it*64*80, Bhi + gb + (size_t)(it*64)*K + k0_); \
            cpa16(B0_ + SB_LO + aoff + it*64*80, Blo + gb + (size_t)(it*64)*K + k0_); \
        }                                                                         \
        asm volatile("cp.async.commit_group;" ::: "memory");                      \
    } while (0)

    ISSUE(0, 0);

    const int wm = (wid >> 2) * 64, wn = (wid & 3) * (NI * 8);
    const int arow = lane & 15, ahalf = lane >> 4;
    const int brow = lane & 7,  bhalf = (lane >> 3) & 1;

    for (int ch = 0; ch < nch; ch++) {
        if (ch + 1 < nch) {
            ISSUE((ch + 1) & 1, ch + 1);
            asm volatile("cp.async.wait_group 1;" ::: "memory");
        } else {
            asm volatile("cp.async.wait_group 0;" ::: "memory");
        }
        __syncthreads();
        const uint32_t base = sb + (ch & 1) * STAGE;

        #pragma unroll
        for (int ks = 0; ks < 2; ks++) {
            uint32_t fahi[4][4], falo[4][4];
            #pragma unroll
            for (int mi = 0; mi < 4; mi++) {
                uint32_t ad = base + (wm + mi * 16 + arow) * 80 + ks * 32 + ahalf * 16;
                ldsm4(fahi[mi], ad);
                ldsm4(falo[mi], ad + SA_LO);
            }
            #pragma unroll
            for (int ni = 0; ni < NI; ni++) {
                uint32_t bd = base + SB_HI + (wn + ni * 8 + brow) * 80 + ks * 32 + bhalf * 16;
                uint32_t fbhi[2], fblo[2];
                ldsm2(fbhi, bd);
                ldsm2(fblo, bd + NI * 2560);
                #pragma unroll
                for (int mi = 0; mi < 4; mi++) {
                    mma_bf16(acc[mi][ni], fahi[mi], fbhi);
                    mma_bf16(acc[mi][ni], fahi[mi], fblo);
                    mma_bf16(acc[mi][ni], falo[mi], fbhi);
                }
            }
        }
        __syncthreads();
    }
#undef ISSUE

    // ---- epilogue ----
    const int qrow = lane >> 2, qcol = (lane & 3) * 2;
    #pragma unroll
    for (int mi = 0; mi < 4; mi++) {
        #pragma unroll
        for (int hh = 0; hh < 2; hh++) {
            const int r = rowBase + wm + mi * 16 + qrow + hh * 8;
            #pragma unroll
            for (int ni = 0; ni < NI; ni++) {
                const int c = nBase + wn + ni * 8 + qcol;
                float v0 = acc[mi][ni][hh * 2 + 0];
                float v1 = acc[mi][ni][hh * 2 + 1];
                if (mode == 0) {
                    if (bias) { v0 += bias[c]; v1 += bias[c + 1]; }
                    *(float2*)(C + (size_t)r * ldC + c) = make_float2(v0, v1);
                } else if (mode == 1) {
                    if (c != r)     C[(size_t)r * ldC + c     - (c     > r ? 1 : 0)] = v0;
                    if (c + 1 != r) C[(size_t)r * ldC + c + 1 - (c + 1 > r ? 1 : 0)] = v1;
                } else if (mode == 2) {
                    if (c < nbound)     C[(size_t)r * ldC + c]     = v0 + bias[c];
                    if (c + 1 < nbound) C[(size_t)r * ldC + c + 1] = v1 + bias[c + 1];
                } else if (mode == 3) {
                    v0 += bias[c]; v1 += bias[c + 1];
                    __nv_bfloat16 h0, l0, h1, l1;
                    split_bf(v0, h0, l0); split_bf(v1, h1, l1);
                    *(__nv_bfloat162*)(Ohi + (size_t)r * ldC + c) = __nv_bfloat162(h0, h1);
                    *(__nv_bfloat162*)(Olo + (size_t)r * ldC + c) = __nv_bfloat162(l0, l1);
                } else {
                    float* Cz = C + (size_t)blockIdx.z * N_SAMP * DIMF;
                    *(float2*)(Cz + (size_t)r * ldC + c) = make_float2(v0, v1);
                }
            }
        }
    }
}

// ============ weight prep: fp32 W[K,N] -> bf16 hi/lo [Npad,K] (transpose + split) ============
__global__ void conv_w(const float* __restrict__ W, __nv_bfloat16* __restrict__ hi,
                       __nv_bfloat16* __restrict__ lo, int K, int N)
{
    __shared__ float ts[32][33];
    const int c = threadIdx.x & 31, r8 = threadIdx.x >> 5;
    const int nb = blockIdx.x * 32, kb = blockIdx.y * 32;
    #pragma unroll
    for (int rr = r8; rr < 32; rr += 8) {
        int n = nb + c;
        ts[rr][c] = (n < N) ? W[(size_t)(kb + rr) * N + n] : 0.f;
    }
    __syncthreads();
    #pragma unroll
    for (int rr = r8; rr < 32; rr += 8) {
        float v = ts[c][rr];
        __nv_bfloat16 h, l; split_bf(v, h, l);
        size_t o = (size_t)(nb + rr) * K + kb + c;
        hi[o] = h; lo[o] = l;
    }
}

// ============ plain split (vectorized): fp32 row-major -> bf16 hi/lo ============
__global__ void conv_plain(const float* __restrict__ X, __nv_bfloat16* __restrict__ hi,
                           __nv_bfloat16* __restrict__ lo, int n4)
{
    int i = blockIdx.x * 256 + threadIdx.x;
    if (i >= n4) return;
    float4 v = ((const float4*)X)[i];
    __nv_bfloat16 h0,l0,h1,l1,h2,l2,h3,l3;
    split_bf(v.x,h0,l0); split_bf(v.y,h1,l1); split_bf(v.z,h2,l2); split_bf(v.w,h3,l3);
    ((__nv_bfloat162*)hi)[i*2]   = __nv_bfloat162(h0,h1);
    ((__nv_bfloat162*)hi)[i*2+1] = __nv_bfloat162(h2,h3);
    ((__nv_bfloat162*)lo)[i*2]   = __nv_bfloat162(l0,l1);
    ((__nv_bfloat162*)lo)[i*2+1] = __nv_bfloat162(l2,l3);
}

// ---------------- batchnorm (deterministic two-stage) ----------------
__global__ void bn_partial(const float* __restrict__ h)
{
    int col = blockIdx.x * 256 + threadIdx.x;
    int r0 = blockIdx.y * 128;
    float s = 0.f, sq = 0.f;
    for (int i = 0; i < 128; i++) {
        float v = h[(size_t)(r0 + i) * DFEAT + col];
        s += v; sq += v * v;
    }
    g_psum[blockIdx.y * DFEAT + col] = s;
    g_psq [blockIdx.y * DFEAT + col] = sq;
}

__global__ void bn_final()
{
    int col = blockIdx.x * 256 + threadIdx.x;
    float s = 0.f, sq = 0.f;
    for (int i = 0; i < 16; i++) { s += g_psum[i * DFEAT + col]; sq += g_psq[i * DFEAT + col]; }
    float mean = s * (1.f / N_SAMP);
    float var  = sq * (1.f / N_SAMP) - mean * mean;
    g_mean[col] = mean;
    g_rstd[col] = rsqrtf(var + 1e-5f);
}

// bn + relu -> write hn as bf16 hi/lo split directly
__global__ void bn_apply(const float* __restrict__ h, const float* __restrict__ gamma,
                         const float* __restrict__ beta,
                         __nv_bfloat16* __restrict__ hi, __nv_bfloat16* __restrict__ lo)
{
    int idx = blockIdx.x * 256 + threadIdx.x;
    int col = (idx * 2) & (DFEAT - 1);
    float2 v2 = ((const float2*)h)[idx];
    float v0 = (v2.x - g_mean[col])   * g_rstd[col]   * gamma[col]   + beta[col];
    float v1 = (v2.y - g_mean[col+1]) * g_rstd[col+1] * gamma[col+1] + beta[col+1];
    v0 = v0 > 0.f ? v0 : 0.f;
    v1 = v1 > 0.f ? v1 : 0.f;
    __nv_bfloat16 h0,l0,h1,l1;
    split_bf(v0,h0,l0); split_bf(v1,h1,l1);
    ((__nv_bfloat162*)hi)[idx] = __nv_bfloat162(h0,h1);
    ((__nv_bfloat162*)lo)[idx] = __nv_bfloat162(l0,l1);
}

// ---------------- feat finalize: reduce split-K partials + bias + L2 norm + split ----------------
__global__ void feat_fix(const float* __restrict__ part, const float* __restrict__ b2,
                         float* __restrict__ feat,
                         __nv_bfloat16* __restrict__ fhi, __nv_bfloat16* __restrict__ flo)
{
    int w = threadIdx.x >> 5, lane = threadIdx.x & 31;
    int row = blockIdx.x * 8 + w;
    float4 v = make_float4(0.f, 0.f, 0.f, 0.f);
    #pragma unroll
    for (int p = 0; p < 4; p++) {
        float4 t = *(const float4*)(part + (size_t)p * N_SAMP * DIMF + (size_t)row * DIMF + lane * 4);
        v.x += t.x; v.y += t.y; v.z += t.z; v.w += t.w;
    }
    float4 b = *(const float4*)(b2 + lane * 4);
    v.x += b.x; v.y += b.y; v.z += b.z; v.w += b.w;
    float ss = v.x * v.x + v.y * v.y + v.z * v.z + v.w * v.w;
    #pragma unroll
    for (int o = 16; o; o >>= 1) ss += __shfl_xor_sync(0xffffffffu, ss, o);
    float r = rsqrtf(ss);
    v.x *= r; v.y *= r; v.z *= r; v.w *= r;
    *(float4*)(feat + (size_t)row * DIMF + lane * 4) = v;
    __nv_bfloat16 h0,l0,h1,l1,h2,l2,h3,l3;
    split_bf(v.x,h0,l0); split_bf(v.y,h1,l1); split_bf(v.z,h2,l2); split_bf(v.w,h3,l3);
    size_t o2 = (size_t)row * (DIMF/2) + lane * 2;
    ((__nv_bfloat162*)fhi)[o2]   = __nv_bfloat162(h0,h1);
    ((__nv_bfloat162*)fhi)[o2+1] = __nv_bfloat162(h2,h3);
    ((__nv_bfloat162*)flo)[o2]   = __nv_bfloat162(l0,l1);
    ((__nv_bfloat162*)flo)[o2+1] = __nv_bfloat162(l2,l3);
}

// ---------------- pos_sel: 4 smallest of 8, ascending ----------------
__global__ void pos_sel(const float* __restrict__ simq, const int* __restrict__ labels,
                        float* __restrict__ out)
{
    int i = blockIdx.x * 256 + threadIdx.x;
    if (i >= N_SAMP) return;
    int L = labels[i];
    float v[8];
    #pragma unroll
    for (int k = 0; k < 8; k++) v[k] = simq[(size_t)i * NQS + L * 8 + k];
    #pragma unroll
    for (int a = 1; a < 8; a++) {
        float x = v[a]; int b = a - 1;
        while (b >= 0 && v[b] > x) { v[b + 1] = v[b]; b--; }
        v[b + 1] = x;
    }
    #pragma unroll
    for (int k = 0; k < 4; k++) out[(size_t)i * NCON + 2047 + k] = v[k];
}

// ---------------- neg top-1024 (sorted desc): radix select + 1024 bitonic ----------------
__global__ void __launch_bounds__(256) neg_topk(const float* __restrict__ simq,
                                                const int* __restrict__ labels,
                                                float* __restrict__ out)
{
    __shared__ uint32_t keys[NEGCNT];
    __shared__ uint32_t buf[KNEG];
    __shared__ int hist[256];
    __shared__ int sh_prefix, sh_target, sh_cnt;
    const int i = blockIdx.x, tid = threadIdx.x;
    const int L = labels[i];
    const size_t base = (size_t)i * NQS;

    for (int t = tid; t < NEGCNT; t += 256) {
        int col = (t < 8 * L) ? t : t + 8;
        uint32_t b = __float_as_uint(simq[base + col]);
        keys[t] = (b >> 31) ? ~b : (b | 0x80000000u);
    }
    if (tid == 0) { sh_target = KNEG; sh_prefix = 0; sh_cnt = 0; }
    __syncthreads();

    uint32_t prefix = 0;
    #pragma unroll
    for (int pass = 0; pass < 4; pass++) {
        const int shift = 24 - pass * 8;
        hist[tid] = 0;
        __syncthreads();
        for (int t = tid; t < NEGCNT; t += 256) {
            uint32_t u = keys[t];
            bool ok = (pass == 0) || ((u >> (shift + 8)) == prefix);
            if (ok) atomicAdd(&hist[(u >> shift) & 255], 1);
        }
        __syncthreads();
        if (tid == 0) {
            int need = sh_target, acc = 0, b = 255;
            while (acc + hist[b] < need) { acc += hist[b]; b--; }
            sh_prefix = (int)((prefix << 8) | (uint32_t)b);
            sh_target = need - acc;
        }
        __syncthreads();
        prefix = (uint32_t)sh_prefix;
    }
    const uint32_t T = prefix;
    const int G = KNEG - sh_target;
    __syncthreads();

    for (int t = tid; t < NEGCNT; t += 256) {
        uint32_t u = keys[t];
        if (u > T) { int p = atomicAdd(&sh_cnt, 1); buf[p] = u; }
    }
    __syncthreads();
    for (int p = G + tid; p < KNEG; p += 256) buf[p] = T;
    __syncthreads();

    for (int k = 2; k <= KNEG; k <<= 1) {
        for (int j = k >> 1; j > 0; j >>= 1) {
            #pragma unroll
            for (int q = 0; q < 4; q++) {
                int t = tid + q * 256;
                int ixj = t ^ j;
                if (ixj > t) {
                    uint32_t a = buf[t], b = buf[ixj];
                    bool up = ((t & k) == 0);
                    if (up ? (a < b) : (a > b)) { buf[t] = b; buf[ixj] = a; }
                }
            }
            __syncthreads();
        }
    }
    #pragma unroll
    for (int q = 0; q < 4; q++) {
        int t = tid + q * 256;
        uint32_t u = buf[t];
        uint32_t bits = (u & 0x80000000u) ? (u & 0x7fffffffu) : ~u;
        out[(size_t)i * NCON + 2051 + t] = __uint_as_float(bits);
    }
}

// ---------------- labels_con ----------------
__global__ void labcon(const int* __restrict__ labels, float* __restrict__ out)
{
    __shared__ int lab[N_SAMP];
    const int i = blockIdx.x;
    for (int t = threadIdx.x; t < N_SAMP; t += blockDim.x) lab[t] = labels[t];
    __syncthreads();
    int Li = lab[i];
    for (int j = threadIdx.x; j < NCON; j += blockDim.x) {
        float v;
        if (j < 2047) { int jj = j + (j >= i ? 1 : 0); v = (Li == lab[jj]) ? 1.f : 0.f; }
        else if (j < 2051) v = 1.f;
        else v = 0.f;
        out[(size_t)i * NCON + j] = v;
    }
}

// ---------------- queue: copy then sequential scan ----------------
__global__ void qcopy(const float* __restrict__ src, float* __restrict__ dst)
{
    int t = blockIdx.x * 256 + threadIdx.x;
    if (t < DIMF * NQ) dst[t] = src[t];
}

__global__ void queue_scan(const float* __restrict__ feat, const int* __restrict__ labels,
                           const int* __restrict__ qptr, float* __restrict__ outq,
                           float* __restrict__ outp)
{
    __shared__ int qp[CC];
    __shared__ int lab[N_SAMP / 2];
    const int tid = threadIdx.x;     // 128 threads, one per dim
    for (int t = tid; t < CC; t += 128) qp[t] = qptr[t];
    for (int t = tid; t < N_SAMP / 2; t += 128) lab[t] = labels[t];
    __syncthreads();
    for (int i = 0; i < N_SAMP / 2; i++) {
        int c = lab[i];
        int ptr = qp[c];
        outq[(size_t)tid * NQ + c * QQ + ptr] = feat[(size_t)i * DIMF + tid];
        __syncthreads();
        if (tid == 0) qp[c] = (ptr + 1) & (QQ - 1);
        __syncthreads();
    }
    for (int t = tid; t < CC; t += 128) outp[t] = (float)qp[t];
}

// ---------------- launch ----------------
extern "C" void kernel_launch(void* const* d_in, const int* in_sizes, int n_in,
                              void* d_out, int out_size)
{
    const float* img    = (const float*)d_in[0];
    const int*   labels = (const int*)  d_in[1];
    const float* qlist  = (const float*)d_in[2];
    const int*   qptr   = (const int*)  d_in[3];
    const float* enc_W  = (const float*)d_in[6];
    const float* enc_b  = (const float*)d_in[7];
    const float* W1     = (const float*)d_in[8];
    const float* b1     = (const float*)d_in[9];
    const float* gamma  = (const float*)d_in[10];
    const float* beta   = (const float*)d_in[11];
    const float* W2     = (const float*)d_in[12];
    const float* b2     = (const float*)d_in[13];
    const float* linW   = (const float*)d_in[14];
    const float* linb   = (const float*)d_in[15];
    float* out = (float*)d_out;

    float *h, *feat, *simq, *fpart;
    __nv_bfloat16 *ahi, *alo, *chi, *clo, *bhi, *blo, *fhi, *flo;
    cudaGetSymbolAddress((void**)&h,     g_h);
    cudaGetSymbolAddress((void**)&feat,  g_feat);
    cudaGetSymbolAddress((void**)&simq,  g_simq);
    cudaGetSymbolAddress((void**)&fpart, g_fpart);
    cudaGetSymbolAddress((void**)&ahi,   g_ahi);
    cudaGetSymbolAddress((void**)&alo,   g_alo);
    cudaGetSymbolAddress((void**)&chi,   g_chi);
    cudaGetSymbolAddress((void**)&clo,   g_clo);
    cudaGetSymbolAddress((void**)&bhi,   g_bhi);
    cudaGetSymbolAddress((void**)&blo,   g_blo);
    cudaGetSymbolAddress((void**)&fhi,   g_fhi);
    cudaGetSymbolAddress((void**)&flo,   g_flo);

    cudaFuncSetAttribute(gemm_mma<8>, cudaFuncAttributeMaxDynamicSharedMemorySize, 122880);
    cudaFuncSetAttribute(gemm_mma<4>, cudaFuncAttributeMaxDynamicSharedMemorySize, 81920);

    // ---- mid(split) = img @ enc_W + enc_b   (K=1024, N=2048; mode 3 -> bf16 split) ----
    conv_plain<<<(N_SAMP * DIN / 4 + 255) / 256, 256>>>(img, chi, clo, N_SAMP * DIN / 4);
    conv_w<<<dim3(DFEAT / 32, DIN / 32), 256>>>(enc_W, bhi, blo, DIN, DFEAT);
    gemm_mma<8><<<dim3(8, 16), 256, 122880>>>(chi, clo, bhi, blo, enc_b, nullptr, ahi, alo,
                                              DIN, DIN, DFEAT, 3, 0);

    // ---- h = mid @ W1 + b1 (fp32), logit = mid @ linW + linb ----
    conv_w<<<dim3(DFEAT / 32, DFEAT / 32), 256>>>(W1, bhi, blo, DFEAT, DFEAT);
    gemm_mma<8><<<dim3(8, 16), 256, 122880>>>(ahi, alo, bhi, blo, b1, h, nullptr, nullptr,
                                              DFEAT, DFEAT, DFEAT, 0, 0);
    conv_w<<<dim3(1024 / 32, DFEAT / 32), 256>>>(linW, bhi, blo, DFEAT, CC);
    gemm_mma<4><<<dim3(8, 16), 256, 81920>>>(ahi, alo, bhi, blo, linb, out + OFF_LOGIT, nullptr, nullptr,
                                             DFEAT, DFEAT, CC, 2, CC);

    // ---- batchnorm + relu -> hn split (into chi/clo) ----
    bn_partial<<<dim3(DFEAT / 256, 16), 256>>>(h);
    bn_final<<<DFEAT / 256, 256>>>();
    bn_apply<<<(N_SAMP * DFEAT / 2) / 256, 256>>>(h, gamma, beta, chi, clo);

    // ---- feat = hn @ W2 + b2 (split-K=4 partials, then fused reduce+norm+split) ----
    conv_w<<<dim3(DIMF / 32, DFEAT / 32), 256>>>(W2, bhi, blo, DFEAT, DIMF);
    gemm_mma<4><<<dim3(1, 16, 4), 256, 81920>>>(chi, clo, bhi, blo, nullptr, fpart, nullptr, nullptr,
                                                DFEAT, DFEAT / 4, DIMF, 4, 0);
    feat_fix<<<N_SAMP / 8, 256>>>(fpart, b2, feat, fhi, flo);

    // ---- sim_b off-diagonal -> sim_con[:, 0:2047] ----
    gemm_mma<8><<<dim3(8, 16), 256, 122880>>>(fhi, flo, fhi, flo, nullptr, out + OFF_SIMCON, nullptr, nullptr,
                                              DIMF, DIMF, NCON, 1, 0);
    // ---- sim_q = feat @ queue_list (N padded 8192) ----
    conv_w<<<dim3(NQS / 32, DIMF / 32), 256>>>(qlist, bhi, blo, DIMF, NQ);
    gemm_mma<8><<<dim3(32, 16), 256, 122880>>>(fhi, flo, bhi, blo, nullptr, simq, nullptr, nullptr,
                                               DIMF, DIMF, NQS, 0, 0);

    // ---- selections ----
    pos_sel<<<N_SAMP / 256, 256>>>(simq, labels, out + OFF_SIMCON);
    neg_topk<<<N_SAMP, 256>>>(simq, labels, out + OFF_SIMCON);
    labcon<<<N_SAMP, 256>>>(labels, out + OFF_LABCON);

    // ---- queue update ----
    qcopy<<<(DIMF * NQ) / 256, 256>>>(qlist, out + OFF_QUEUE);
    queue_scan<<<1, 128>>>(feat, labels, qptr, out + OFF_QUEUE, out + OFF_QPTR);
}

// round 6
// speedup vs baseline: 3.8920x; 1.3008x over previous
#include <cuda_runtime.h>
#include <cuda_bf16.h>
#include <cstdint>

#define N_SAMP 2048
#define DIN    1024
#define DFEAT  2048
#define DIMF   128
#define CC     1000
#define QQ     8
#define NQ     8000
#define NQS    8192      // padded sim_q stride
#define KNEG   1024
#define NCON   3075      // 2047 + 4 + 1024
#define NEGCNT 7992

// output layout (float32, tuple order, row-major flattened)
#define OFF_SIMCON 0ull
#define OFF_LABCON 6297600ull
#define OFF_LOGIT  12595200ull
#define OFF_QUEUE  14643200ull
#define OFF_QPTR   15667200ull

// ---------------- device scratch ----------------
__device__ float g_h   [N_SAMP * DFEAT];
__device__ float g_simq[N_SAMP * NQS];
__device__ float g_feat[N_SAMP * DIMF];
__device__ float g_fpart[4 * N_SAMP * DIMF];
__device__ float g_psum[16 * DFEAT];
__device__ float g_psq [16 * DFEAT];
__device__ float g_mean[DFEAT];
__device__ float g_rstd[DFEAT];
__device__ int   g_win [1024];
__device__ __nv_bfloat16 g_ahi[N_SAMP * DFEAT];   // mid split
__device__ __nv_bfloat16 g_alo[N_SAMP * DFEAT];
__device__ __nv_bfloat16 g_chi[N_SAMP * DFEAT];   // img split, then hn split
__device__ __nv_bfloat16 g_clo[N_SAMP * DFEAT];
__device__ __nv_bfloat16 g_fhi[N_SAMP * DIMF];    // feat split
__device__ __nv_bfloat16 g_flo[N_SAMP * DIMF];
// weight splits (transposed [N][K])
__device__ __nv_bfloat16 g_ehi [DFEAT * DIN];
__device__ __nv_bfloat16 g_elo [DFEAT * DIN];
__device__ __nv_bfloat16 g_w1hi[DFEAT * DFEAT];
__device__ __nv_bfloat16 g_w1lo[DFEAT * DFEAT];
__device__ __nv_bfloat16 g_lnhi[1024 * DFEAT];
__device__ __nv_bfloat16 g_lnlo[1024 * DFEAT];
__device__ __nv_bfloat16 g_w2hi[DIMF * DFEAT];
__device__ __nv_bfloat16 g_w2lo[DIMF * DFEAT];
__device__ __nv_bfloat16 g_qhi [NQS * DIMF];
__device__ __nv_bfloat16 g_qlo [NQS * DIMF];

// ================= helpers =================
__device__ __forceinline__ uint32_t smem_u32(const void* p) {
    uint32_t a;
    asm("{ .reg .u64 t; cvta.to.shared.u64 t, %1; cvt.u32.u64 %0, t; }" : "=r"(a) : "l"(p));
    return a;
}
__device__ __forceinline__ void cpa16(uint32_t s, const void* g) {
    asm volatile("cp.async.cg.shared.global [%0], [%1], 16;" :: "r"(s), "l"(g) : "memory");
}
__device__ __forceinline__ void ldsm4(uint32_t* r, uint32_t addr) {
    asm volatile("ldmatrix.sync.aligned.m8n8.x4.shared.b16 {%0,%1,%2,%3}, [%4];"
                 : "=r"(r[0]), "=r"(r[1]), "=r"(r[2]), "=r"(r[3]) : "r"(addr));
}
__device__ __forceinline__ void ldsm2(uint32_t* r, uint32_t addr) {
    asm volatile("ldmatrix.sync.aligned.m8n8.x2.shared.b16 {%0,%1}, [%2];"
                 : "=r"(r[0]), "=r"(r[1]) : "r"(addr));
}
__device__ __forceinline__ void mma_bf16(float* c, const uint32_t* a, const uint32_t* b) {
    asm volatile("mma.sync.aligned.m16n8k16.row.col.f32.bf16.bf16.f32 "
                 "{%0,%1,%2,%3}, {%4,%5,%6,%7}, {%8,%9}, {%0,%1,%2,%3};"
                 : "+f"(c[0]), "+f"(c[1]), "+f"(c[2]), "+f"(c[3])
                 : "r"(a[0]), "r"(a[1]), "r"(a[2]), "r"(a[3]), "r"(b[0]), "r"(b[1]));
}
__device__ __forceinline__ void split_bf(float v, __nv_bfloat16& h, __nv_bfloat16& l) {
    h = __float2bfloat16(v);
    l = __float2bfloat16(v - __bfloat162float(h));
}

// ================= split-bf16 MMA GEMM: C[M x Ntile*grid] = A @ B^T =================
// Tile 128 x (NI*32). BK=32, double-buffered cp.async, 3-pass split accuracy.
// mode: 0 fp32(+bias), 1 offdiag-compact, 2 bounded cols(+bias), 3 bf16 split out(+bias),
//       4 split-K partial fp32 (offset blockIdx.z)
template<int NI>
__global__ void __launch_bounds__(256, 1) gemm_mma(
    const __nv_bfloat16* __restrict__ Ahi, const __nv_bfloat16* __restrict__ Alo,
    const __nv_bfloat16* __restrict__ Bhi, const __nv_bfloat16* __restrict__ Blo,
    const float* __restrict__ bias, float* __restrict__ C,
    __nv_bfloat16* __restrict__ Ohi, __nv_bfloat16* __restrict__ Olo,
    int K, int Ksub, int ldC, int mode, int nbound)
{
    constexpr uint32_t SA_LO = 10240;              // 128*80
    constexpr uint32_t SB_HI = 20480;
    constexpr uint32_t SB_LO = 20480 + NI * 2560;  // NI*32*80
    constexpr uint32_t STAGE = 20480 + 2 * NI * 2560;

    extern __shared__ __align__(128) char sm[];
    const uint32_t sb = smem_u32(sm);
    const int tid = threadIdx.x, wid = tid >> 5, lane = tid & 31;
    const int rowBase = blockIdx.y * 128, nBase = blockIdx.x * (NI * 32);
    const int kbase = blockIdx.z * Ksub;
    const int nch = Ksub >> 5;

    float acc[4][NI][4];
    #pragma unroll
    for (int i = 0; i < 4; i++)
        #pragma unroll
        for (int j = 0; j < NI; j++)
            #pragma unroll
            for (int q = 0; q < 4; q++) acc[i][j][q] = 0.f;

    const int ldRow = tid >> 2, ldSeg = tid & 3;
    const uint32_t aoff = ldRow * 80 + ldSeg * 16;
    const size_t ga = (size_t)(rowBase + ldRow) * K + ldSeg * 8 + kbase;
    const size_t gb = (size_t)(nBase  + ldRow) * K + ldSeg * 8 + kbase;

#define ISSUE(st, ch) do {                                                        \
        const int k0_ = (ch) << 5;                                                \
        const uint32_t B0_ = sb + (st) * STAGE;                                   \
        cpa16(B0_ + aoff,                 Ahi + ga + k0_);                        \
        cpa16(B0_ + aoff + 64*80,         Ahi + ga + (size_t)64*K + k0_);         \
        cpa16(B0_ + SA_LO + aoff,         Alo + ga + k0_);                        \
        cpa16(B0_ + SA_LO + aoff + 64*80, Alo + ga + (size_t)64*K + k0_);         \
        _Pragma("unroll")                                                         \
        for (int it = 0; it < NI / 2; it++) {                                     \
            cpa16(B0_ + SB_HI + aoff + it*64*80, Bhi + gb + (size_t)(it*64)*K + k0_); \
            cpa16(B0_ + SB_LO + aoff + it*64*80, Blo + gb + (size_t)(it*64)*K + k0_); \
        }                                                                         \
        asm volatile("cp.async.commit_group;" ::: "memory");                      \
    } while (0)

    ISSUE(0, 0);

    const int wm = (wid >> 2) * 64, wn = (wid & 3) * (NI * 8);
    const int arow = lane & 15, ahalf = lane >> 4;
    const int brow = lane & 7,  bhalf = (lane >> 3) & 1;

    for (int ch = 0; ch < nch; ch++) {
        if (ch + 1 < nch) {
            ISSUE((ch + 1) & 1, ch + 1);
            asm volatile("cp.async.wait_group 1;" ::: "memory");
        } else {
            asm volatile("cp.async.wait_group 0;" ::: "memory");
        }
        __syncthreads();
        const uint32_t base = sb + (ch & 1) * STAGE;

        #pragma unroll
        for (int ks = 0; ks < 2; ks++) {
            uint32_t fahi[4][4], falo[4][4];
            #pragma unroll
            for (int mi = 0; mi < 4; mi++) {
                uint32_t ad = base + (wm + mi * 16 + arow) * 80 + ks * 32 + ahalf * 16;
                ldsm4(fahi[mi], ad);
                ldsm4(falo[mi], ad + SA_LO);
            }
            #pragma unroll
            for (int ni = 0; ni < NI; ni++) {
                uint32_t bd = base + SB_HI + (wn + ni * 8 + brow) * 80 + ks * 32 + bhalf * 16;
                uint32_t fbhi[2], fblo[2];
                ldsm2(fbhi, bd);
                ldsm2(fblo, bd + NI * 2560);
                #pragma unroll
                for (int mi = 0; mi < 4; mi++) {
                    mma_bf16(acc[mi][ni], fahi[mi], fbhi);
                    mma_bf16(acc[mi][ni], fahi[mi], fblo);
                    mma_bf16(acc[mi][ni], falo[mi], fbhi);
                }
            }
        }
        __syncthreads();
    }
#undef ISSUE

    // ---- epilogue ----
    const int qrow = lane >> 2, qcol = (lane & 3) * 2;
    #pragma unroll
    for (int mi = 0; mi < 4; mi++) {
        #pragma unroll
        for (int hh = 0; hh < 2; hh++) {
            const int r = rowBase + wm + mi * 16 + qrow + hh * 8;
            #pragma unroll
            for (int ni = 0; ni < NI; ni++) {
                const int c = nBase + wn + ni * 8 + qcol;
                float v0 = acc[mi][ni][hh * 2 + 0];
                float v1 = acc[mi][ni][hh * 2 + 1];
                if (mode == 0) {
                    if (bias) { v0 += bias[c]; v1 += bias[c + 1]; }
                    *(float2*)(C + (size_t)r * ldC + c) = make_float2(v0, v1);
                } else if (mode == 1) {
                    if (c != r)     C[(size_t)r * ldC + c     - (c     > r ? 1 : 0)] = v0;
                    if (c + 1 != r) C[(size_t)r * ldC + c + 1 - (c + 1 > r ? 1 : 0)] = v1;
                } else if (mode == 2) {
                    if (c < nbound)     C[(size_t)r * ldC + c]     = v0 + bias[c];
                    if (c + 1 < nbound) C[(size_t)r * ldC + c + 1] = v1 + bias[c + 1];
                } else if (mode == 3) {
                    v0 += bias[c]; v1 += bias[c + 1];
                    __nv_bfloat16 h0, l0, h1, l1;
                    split_bf(v0, h0, l0); split_bf(v1, h1, l1);
                    *(__nv_bfloat162*)(Ohi + (size_t)r * ldC + c) = __nv_bfloat162(h0, h1);
                    *(__nv_bfloat162*)(Olo + (size_t)r * ldC + c) = __nv_bfloat162(l0, l1);
                } else {
                    float* Cz = C + (size_t)blockIdx.z * N_SAMP * DIMF;
                    *(float2*)(Cz + (size_t)r * ldC + c) = make_float2(v0, v1);
                }
            }
        }
    }
}

// ============ all weight conversions in one kernel (transpose + split, bf162 stores) ============
__global__ void conv_all(const float* __restrict__ encW, const float* __restrict__ W1,
                         const float* __restrict__ linW, const float* __restrict__ W2,
                         const float* __restrict__ ql,
                         __nv_bfloat16* ehi, __nv_bfloat16* elo,
                         __nv_bfloat16* w1hi, __nv_bfloat16* w1lo,
                         __nv_bfloat16* lnhi, __nv_bfloat16* lnlo,
                         __nv_bfloat16* w2hi, __nv_bfloat16* w2lo,
                         __nv_bfloat16* qhi,  __nv_bfloat16* qlo)
{
    __shared__ float ts[32][33];
    const int b = blockIdx.x;
    const float* W; __nv_bfloat16 *hi, *lo; int K, N, nx, id;
    if (b < 2048)      { W = encW; hi = ehi;  lo = elo;  K = 1024; N = 2048; nx = 64;  id = b; }
    else if (b < 6144) { W = W1;   hi = w1hi; lo = w1lo; K = 2048; N = 2048; nx = 64;  id = b - 2048; }
    else if (b < 8192) { W = linW; hi = lnhi; lo = lnlo; K = 2048; N = 1000; nx = 32;  id = b - 6144; }
    else if (b < 8448) { W = W2;   hi = w2hi; lo = w2lo; K = 2048; N = 128;  nx = 4;   id = b - 8192; }
    else               { W = ql;   hi = qhi;  lo = qlo;  K = 128;  N = 8000; nx = 256; id = b - 8448; }
    const int nb = (id % nx) * 32, kb = (id / nx) * 32;

    const int c = threadIdx.x & 31, r8 = threadIdx.x >> 5;
    #pragma unroll
    for (int rr = r8; rr < 32; rr += 8) {
        int n = nb + c;
        ts[rr][c] = (n < N) ? W[(size_t)(kb + rr) * N + n] : 0.f;
    }
    __syncthreads();
    const int c16 = threadIdx.x & 15, rh = threadIdx.x >> 4;
    #pragma unroll
    for (int rr = rh; rr < 32; rr += 16) {
        float v0 = ts[2 * c16][rr], v1 = ts[2 * c16 + 1][rr];
        __nv_bfloat16 h0, l0, h1, l1;
        split_bf(v0, h0, l0); split_bf(v1, h1, l1);
        size_t o = (size_t)(nb + rr) * K + kb;
        ((__nv_bfloat162*)(hi + o))[c16] = __nv_bfloat162(h0, h1);
        ((__nv_bfloat162*)(lo + o))[c16] = __nv_bfloat162(l0, l1);
    }
}

// ============ plain split (vectorized): fp32 row-major -> bf16 hi/lo ============
__global__ void conv_plain(const float* __restrict__ X, __nv_bfloat16* __restrict__ hi,
                           __nv_bfloat16* __restrict__ lo, int n4)
{
    int i = blockIdx.x * 256 + threadIdx.x;
    if (i >= n4) return;
    float4 v = ((const float4*)X)[i];
    __nv_bfloat16 h0,l0,h1,l1,h2,l2,h3,l3;
    split_bf(v.x,h0,l0); split_bf(v.y,h1,l1); split_bf(v.z,h2,l2); split_bf(v.w,h3,l3);
    ((__nv_bfloat162*)hi)[i*2]   = __nv_bfloat162(h0,h1);
    ((__nv_bfloat162*)hi)[i*2+1] = __nv_bfloat162(h2,h3);
    ((__nv_bfloat162*)lo)[i*2]   = __nv_bfloat162(l0,l1);
    ((__nv_bfloat162*)lo)[i*2+1] = __nv_bfloat162(l2,l3);
}

// ---------------- batchnorm (deterministic two-stage) ----------------
__global__ void bn_partial(const float* __restrict__ h)
{
    int col = blockIdx.x * 256 + threadIdx.x;
    int r0 = blockIdx.y * 128;
    float s = 0.f, sq = 0.f;
    for (int i = 0; i < 128; i++) {
        float v = h[(size_t)(r0 + i) * DFEAT + col];
        s += v; sq += v * v;
    }
    g_psum[blockIdx.y * DFEAT + col] = s;
    g_psq [blockIdx.y * DFEAT + col] = sq;
}

__global__ void bn_final()
{
    int col = blockIdx.x * 256 + threadIdx.x;
    float s = 0.f, sq = 0.f;
    for (int i = 0; i < 16; i++) { s += g_psum[i * DFEAT + col]; sq += g_psq[i * DFEAT + col]; }
    float mean = s * (1.f / N_SAMP);
    float var  = sq * (1.f / N_SAMP) - mean * mean;
    g_mean[col] = mean;
    g_rstd[col] = rsqrtf(var + 1e-5f);
}

__global__ void bn_apply(const float* __restrict__ h, const float* __restrict__ gamma,
                         const float* __restrict__ beta,
                         __nv_bfloat16* __restrict__ hi, __nv_bfloat16* __restrict__ lo)
{
    int idx = blockIdx.x * 256 + threadIdx.x;
    int col = (idx * 2) & (DFEAT - 1);
    float2 v2 = ((const float2*)h)[idx];
    float v0 = (v2.x - g_mean[col])   * g_rstd[col]   * gamma[col]   + beta[col];
    float v1 = (v2.y - g_mean[col+1]) * g_rstd[col+1] * gamma[col+1] + beta[col+1];
    v0 = v0 > 0.f ? v0 : 0.f;
    v1 = v1 > 0.f ? v1 : 0.f;
    __nv_bfloat16 h0,l0,h1,l1;
    split_bf(v0,h0,l0); split_bf(v1,h1,l1);
    ((__nv_bfloat162*)hi)[idx] = __nv_bfloat162(h0,h1);
    ((__nv_bfloat162*)lo)[idx] = __nv_bfloat162(l0,l1);
}

// ---------------- feat finalize: reduce split-K partials + bias + L2 norm + split ----------------
__global__ void feat_fix(const float* __restrict__ part, const float* __restrict__ b2,
                         float* __restrict__ feat,
                         __nv_bfloat16* __restrict__ fhi, __nv_bfloat16* __restrict__ flo)
{
    int w = threadIdx.x >> 5, lane = threadIdx.x & 31;
    int row = blockIdx.x * 8 + w;
    float4 v = make_float4(0.f, 0.f, 0.f, 0.f);
    #pragma unroll
    for (int p = 0; p < 4; p++) {
        float4 t = *(const float4*)(part + (size_t)p * N_SAMP * DIMF + (size_t)row * DIMF + lane * 4);
        v.x += t.x; v.y += t.y; v.z += t.z; v.w += t.w;
    }
    float4 b = *(const float4*)(b2 + lane * 4);
    v.x += b.x; v.y += b.y; v.z += b.z; v.w += b.w;
    float ss = v.x * v.x + v.y * v.y + v.z * v.z + v.w * v.w;
    #pragma unroll
    for (int o = 16; o; o >>= 1) ss += __shfl_xor_sync(0xffffffffu, ss, o);
    float r = rsqrtf(ss);
    v.x *= r; v.y *= r; v.z *= r; v.w *= r;
    *(float4*)(feat + (size_t)row * DIMF + lane * 4) = v;
    __nv_bfloat16 h0,l0,h1,l1,h2,l2,h3,l3;
    split_bf(v.x,h0,l0); split_bf(v.y,h1,l1); split_bf(v.z,h2,l2); split_bf(v.w,h3,l3);
    size_t o2 = (size_t)row * (DIMF/2) + lane * 2;
    ((__nv_bfloat162*)fhi)[o2]   = __nv_bfloat162(h0,h1);
    ((__nv_bfloat162*)fhi)[o2+1] = __nv_bfloat162(h2,h3);
    ((__nv_bfloat162*)flo)[o2]   = __nv_bfloat162(l0,l1);
    ((__nv_bfloat162*)flo)[o2+1] = __nv_bfloat162(l2,l3);
}

// ---------------- fused selections: labels_con + pos_sel + neg top-1024 ----------------
__global__ void __launch_bounds__(256) sel_fused(const float* __restrict__ simq,
                                                 const int* __restrict__ labels,
                                                 float* __restrict__ out)
{
    __shared__ uint32_t keys[NEGCNT];
    __shared__ uint32_t buf[KNEG];
    __shared__ int lab[N_SAMP];
    __shared__ int hist[256];
    __shared__ int sh_prefix, sh_target, sh_cnt;
    const int i = blockIdx.x, tid = threadIdx.x;
    const size_t base = (size_t)i * NQS;

    for (int t = tid; t < N_SAMP; t += 256) lab[t] = labels[t];
    if (tid == 0) { sh_target = KNEG; sh_prefix = 0; sh_cnt = 0; }
    __syncthreads();
    const int L = lab[i];

    // labels_con row i
    float* labrow = out + OFF_LABCON + (size_t)i * NCON;
    for (int j = tid; j < 2047; j += 256) {
        int jj = j + (j >= i ? 1 : 0);
        labrow[j] = (L == lab[jj]) ? 1.f : 0.f;
    }
    for (int j = 2047 + tid; j < NCON; j += 256) labrow[j] = (j < 2051) ? 1.f : 0.f;

    // pos_sel: 4 smallest of 8 (ascending)
    if (tid == 0) {
        float v[8];
        #pragma unroll
        for (int k = 0; k < 8; k++) v[k] = simq[base + L * 8 + k];
        #pragma unroll
        for (int a = 1; a < 8; a++) {
            float x = v[a]; int bb = a - 1;
            while (bb >= 0 && v[bb] > x) { v[bb + 1] = v[bb]; bb--; }
            v[bb + 1] = x;
        }
        #pragma unroll
        for (int k = 0; k < 4; k++) out[(size_t)i * NCON + 2047 + k] = v[k];
    }

    // neg keys (order-preserving uint transform)
    for (int t = tid; t < NEGCNT; t += 256) {
        int col = (t < 8 * L) ? t : t + 8;
        uint32_t b = __float_as_uint(simq[base + col]);
        keys[t] = (b >> 31) ? ~b : (b | 0x80000000u);
    }
    __syncthreads();

    uint32_t prefix = 0;
    #pragma unroll
    for (int pass = 0; pass < 4; pass++) {
        const int shift = 24 - pass * 8;
        hist[tid] = 0;
        __syncthreads();
        for (int t = tid; t < NEGCNT; t += 256) {
            uint32_t u = keys[t];
            bool ok = (pass == 0) || ((u >> (shift + 8)) == prefix);
            if (ok) atomicAdd(&hist[(u >> shift) & 255], 1);
        }
        __syncthreads();
        if (tid == 0) {
            int need = sh_target, acc = 0, b = 255;
            while (acc + hist[b] < need) { acc += hist[b]; b--; }
            sh_prefix = (int)((prefix << 8) | (uint32_t)b);
            sh_target = need - acc;
        }
        __syncthreads();
        prefix = (uint32_t)sh_prefix;
    }
    const uint32_t T = prefix;
    const int G = KNEG - sh_target;
    __syncthreads();

    for (int t = tid; t < NEGCNT; t += 256) {
        uint32_t u = keys[t];
        if (u > T) { int p = atomicAdd(&sh_cnt, 1); buf[p] = u; }
    }
    __syncthreads();
    for (int p = G + tid; p < KNEG; p += 256) buf[p] = T;
    __syncthreads();

    for (int k = 2; k <= KNEG; k <<= 1) {
        for (int j = k >> 1; j > 0; j >>= 1) {
            #pragma unroll
            for (int q = 0; q < 4; q++) {
                int t = tid + q * 256;
                int ixj = t ^ j;
                if (ixj > t) {
                    uint32_t a = buf[t], b = buf[ixj];
                    bool up = ((t & k) == 0);
                    if (up ? (a < b) : (a > b)) { buf[t] = b; buf[ixj] = a; }
                }
            }
            __syncthreads();
        }
    }
    #pragma unroll
    for (int q = 0; q < 4; q++) {
        int t = tid + q * 256;
        uint32_t u = buf[t];
        uint32_t bits = (u & 0x80000000u) ? (u & 0x7fffffffu) : ~u;
        out[(size_t)i * NCON + 2051 + t] = __uint_as_float(bits);
    }
}

// ---------------- queue: parallel rank-based update ----------------
__global__ void __launch_bounds__(1024) qprep(const int* __restrict__ labels,
                                              const int* __restrict__ qptr,
                                              int* __restrict__ win, float* __restrict__ outp)
{
    __shared__ int lab[1024];
    __shared__ int cnt[CC];
    const int tid = threadIdx.x;
    lab[tid] = labels[tid];
    if (tid < CC) cnt[tid] = 0;
    __syncthreads();
    const int L = lab[tid];
    atomicAdd(&cnt[L], 1);
    int rank = 0;
    for (int j = 0; j < 1024; j++)
        if (j < tid && lab[j] == L) rank++;
    __syncthreads();
    const int tot = cnt[L];
    int slot = -1;
    if (rank >= tot - 8) slot = L * QQ + ((qptr[L] + rank) & (QQ - 1));
    win[tid] = slot;
    if (tid < CC) outp[tid] = (float)((qptr[tid] + cnt[tid]) & (QQ - 1));
}

__global__ void qcopy(const float* __restrict__ src, float* __restrict__ dst)
{
    int t = blockIdx.x * 256 + threadIdx.x;
    if (t < DIMF * NQ) dst[t] = src[t];
}

__global__ void qwrite(const float* __restrict__ feat, const int* __restrict__ win,
                       float* __restrict__ outq)
{
    int s = win[blockIdx.x];
    if (s < 0) return;
    outq[(size_t)threadIdx.x * NQ + s] = feat[(size_t)blockIdx.x * DIMF + threadIdx.x];
}

// ---------------- launch ----------------
extern "C" void kernel_launch(void* const* d_in, const int* in_sizes, int n_in,
                              void* d_out, int out_size)
{
    const float* img    = (const float*)d_in[0];
    const int*   labels = (const int*)  d_in[1];
    const float* qlist  = (const float*)d_in[2];
    const int*   qptr   = (const int*)  d_in[3];
    const float* enc_W  = (const float*)d_in[6];
    const float* enc_b  = (const float*)d_in[7];
    const float* W1     = (const float*)d_in[8];
    const float* b1     = (const float*)d_in[9];
    const float* gamma  = (const float*)d_in[10];
    const float* beta   = (const float*)d_in[11];
    const float* W2     = (const float*)d_in[12];
    const float* b2     = (const float*)d_in[13];
    const float* linW   = (const float*)d_in[14];
    const float* linb   = (const float*)d_in[15];
    float* out = (float*)d_out;

    float *h, *feat, *simq, *fpart; int* win;
    __nv_bfloat16 *ahi, *alo, *chi, *clo, *fhi, *flo;
    __nv_bfloat16 *ehi, *elo, *w1hi, *w1lo, *lnhi, *lnlo, *w2hi, *w2lo, *qhi, *qlo;
    cudaGetSymbolAddress((void**)&h,     g_h);
    cudaGetSymbolAddress((void**)&feat,  g_feat);
    cudaGetSymbolAddress((void**)&simq,  g_simq);
    cudaGetSymbolAddress((void**)&fpart, g_fpart);
    cudaGetSymbolAddress((void**)&win,   g_win);
    cudaGetSymbolAddress((void**)&ahi,   g_ahi);
    cudaGetSymbolAddress((void**)&alo,   g_alo);
    cudaGetSymbolAddress((void**)&chi,   g_chi);
    cudaGetSymbolAddress((void**)&clo,   g_clo);
    cudaGetSymbolAddress((void**)&fhi,   g_fhi);
    cudaGetSymbolAddress((void**)&flo,   g_flo);
    cudaGetSymbolAddress((void**)&ehi,   g_ehi);
    cudaGetSymbolAddress((void**)&elo,   g_elo);
    cudaGetSymbolAddress((void**)&w1hi,  g_w1hi);
    cudaGetSymbolAddress((void**)&w1lo,  g_w1lo);
    cudaGetSymbolAddress((void**)&lnhi,  g_lnhi);
    cudaGetSymbolAddress((void**)&lnlo,  g_lnlo);
    cudaGetSymbolAddress((void**)&w2hi,  g_w2hi);
    cudaGetSymbolAddress((void**)&w2lo,  g_w2lo);
    cudaGetSymbolAddress((void**)&qhi,   g_qhi);
    cudaGetSymbolAddress((void**)&qlo,   g_qlo);

    cudaFuncSetAttribute(gemm_mma<8>, cudaFuncAttributeMaxDynamicSharedMemorySize, 122880);
    cudaFuncSetAttribute(gemm_mma<4>, cudaFuncAttributeMaxDynamicSharedMemorySize, 81920);

    // all weight conversions + img split
    conv_all<<<9472, 256>>>(enc_W, W1, linW, W2, qlist,
                            ehi, elo, w1hi, w1lo, lnhi, lnlo, w2hi, w2lo, qhi, qlo);
    conv_plain<<<(N_SAMP * DIN / 4 + 255) / 256, 256>>>(img, chi, clo, N_SAMP * DIN / 4);

    // mid(split) = img @ enc_W + enc_b
    gemm_mma<8><<<dim3(8, 16), 256, 122880>>>(chi, clo, ehi, elo, enc_b, nullptr, ahi, alo,
                                              DIN, DIN, DFEAT, 3, 0);
    // h = mid @ W1 + b1 ; logit = mid @ linW + linb
    gemm_mma<8><<<dim3(8, 16), 256, 122880>>>(ahi, alo, w1hi, w1lo, b1, h, nullptr, nullptr,
                                              DFEAT, DFEAT, DFEAT, 0, 0);
    gemm_mma<4><<<dim3(8, 16), 256, 81920>>>(ahi, alo, lnhi, lnlo, linb, out + OFF_LOGIT, nullptr, nullptr,
                                             DFEAT, DFEAT, CC, 2, CC);
    // batchnorm + relu -> hn split
    bn_partial<<<dim3(DFEAT / 256, 16), 256>>>(h);
    bn_final<<<DFEAT / 256, 256>>>();
    bn_apply<<<(N_SAMP * DFEAT / 2) / 256, 256>>>(h, gamma, beta, chi, clo);
    // feat = hn @ W2 + b2 (split-K=4), then fused norm+split
    gemm_mma<4><<<dim3(1, 16, 4), 256, 81920>>>(chi, clo, w2hi, w2lo, nullptr, fpart, nullptr, nullptr,
                                                DFEAT, DFEAT / 4, DIMF, 4, 0);
    feat_fix<<<N_SAMP / 8, 256>>>(fpart, b2, feat, fhi, flo);
    // sim_b off-diagonal
    gemm_mma<8><<<dim3(8, 16), 256, 122880>>>(fhi, flo, fhi, flo, nullptr, out + OFF_SIMCON, nullptr, nullptr,
                                              DIMF, DIMF, NCON, 1, 0);
    // sim_q
    gemm_mma<8><<<dim3(32, 16), 256, 122880>>>(fhi, flo, qhi, qlo, nullptr, simq, nullptr, nullptr,
                                               DIMF, DIMF, NQS, 0, 0);
    // fused selections (labcon + pos + neg)
    sel_fused<<<N_SAMP, 256>>>(simq, labels, out);
    // queue update (parallel)
    qprep<<<1, 1024>>>(labels, qptr, win, out + OFF_QPTR);
    qcopy<<<(DIMF * NQ + 255) / 256, 256>>>(qlist, out + OFF_QUEUE);
    qwrite<<<1024, 128>>>(feat, win, out + OFF_QUEUE);
}